// round 2
// baseline (speedup 1.0000x reference)
#include <cuda_runtime.h>
#include <cstddef>

// Problem constants
#define TT   1024
#define BBATCH 128
#define DD   128
#define HH   256
#define RTOT (TT * BBATCH)   /* 131072 flat rows */
#define G4H  1024            /* 4*H gate columns */

typedef unsigned long long ull;

// ---------------------------------------------------------------------------
// Scratch (static device globals — no allocation APIs allowed)
// ---------------------------------------------------------------------------
__device__ float g_xg[(size_t)RTOT * G4H];   // 512 MB: per-layer input-gate staging
__device__ float g_tmp[(size_t)RTOT * HH];   // 128 MB: inter-layer activation buffer
__device__ unsigned g_bar_cnt = 0;
__device__ unsigned g_bar_gen = 0;

// ---------------------------------------------------------------------------
// f32x2 packed-FMA helpers (FFMA2: 2x FFMA-3reg throughput on sm_103a)
// ---------------------------------------------------------------------------
__device__ __forceinline__ void fma2(ull& d, ull a, ull b) {
    asm("fma.rn.f32x2 %0, %1, %2, %0;" : "+l"(d) : "l"(a), "l"(b));
}
__device__ __forceinline__ ull pack2(float lo, float hi) {
    ull r;
    asm("mov.b64 %0, {%1, %2};" : "=l"(r)
        : "r"(__float_as_uint(lo)), "r"(__float_as_uint(hi)));
    return r;
}
__device__ __forceinline__ float2 unpack2(ull v) {
    unsigned lo, hi;
    asm("mov.b64 {%0, %1}, %2;" : "=r"(lo), "=r"(hi) : "l"(v));
    return make_float2(__uint_as_float(lo), __uint_as_float(hi));
}

// Fast-but-accurate activations (MUFU ex2 based; abs err ~1e-7)
__device__ __forceinline__ float sigf(float x) {
    return __fdividef(1.f, 1.f + __expf(-x));
}
__device__ __forceinline__ float tanh_fast(float x) {
    // 2*sigmoid(2x)-1: well behaved at +/-inf, abs err ~1e-7
    return 2.f * sigf(2.f * x) - 1.f;
}

// ---------------------------------------------------------------------------
// GEMM: g_xg[r][n] = sum_k A[r][k] * W[n][k] + bih[n] + bhh[n]
// A: [RTOT, K] row-major, W: [1024, K] row-major. Tiles 128x64, BK=16.
// f32x2 column-pair accumulators.
// ---------------------------------------------------------------------------
template <int K>
__global__ void __launch_bounds__(256) gemm_xg_kernel(
    const float* __restrict__ A, const float* __restrict__ W,
    const float* __restrict__ bih, const float* __restrict__ bhh)
{
    __shared__ float Asm[16][132];  // [k][m], padded
    __shared__ float Bsm[16][68];   // [k][n], padded

    const int tid  = threadIdx.x;
    const int nb   = blockIdx.x;        // 0..15   (64-col blocks)
    const int mb   = blockIdx.y;        // 0..1023 (128-row blocks)
    const int tm   = tid >> 4;          // 0..15
    const int tn   = tid & 15;          // 0..15
    const int row0 = mb * 128;
    const int col0 = nb * 64;

    float bias[4];
#pragma unroll
    for (int j = 0; j < 4; ++j)
        bias[j] = bih[col0 + tn * 4 + j] + bhh[col0 + tn * 4 + j];

    ull acc[8][2];
#pragma unroll
    for (int i = 0; i < 8; ++i) { acc[i][0] = 0ull; acc[i][1] = 0ull; }

    const int ar0 = tid >> 2;          // 0..63 (A-load row within half-tile)
    const int akv = (tid & 3) * 4;     // k sub-offset 0/4/8/12
    const int wn  = tid >> 2;          // 0..63 (W-load n)
    const int wkv = (tid & 3) * 4;

    for (int k0 = 0; k0 < K; k0 += 16) {
#pragma unroll
        for (int h = 0; h < 2; ++h) {
            int r = ar0 + h * 64;
            float4 v = *(const float4*)&A[(size_t)(row0 + r) * K + k0 + akv];
            Asm[akv + 0][r] = v.x; Asm[akv + 1][r] = v.y;
            Asm[akv + 2][r] = v.z; Asm[akv + 3][r] = v.w;
        }
        {
            float4 v = *(const float4*)&W[(size_t)(col0 + wn) * K + k0 + wkv];
            Bsm[wkv + 0][wn] = v.x; Bsm[wkv + 1][wn] = v.y;
            Bsm[wkv + 2][wn] = v.z; Bsm[wkv + 3][wn] = v.w;
        }
        __syncthreads();

#pragma unroll
        for (int k = 0; k < 16; ++k) {
            float4 a0 = *(const float4*)&Asm[k][tm * 8];
            float4 a1 = *(const float4*)&Asm[k][tm * 8 + 4];
            float4 b  = *(const float4*)&Bsm[k][tn * 4];
            ull b01 = pack2(b.x, b.y);
            ull b23 = pack2(b.z, b.w);
            float am[8] = {a0.x, a0.y, a0.z, a0.w, a1.x, a1.y, a1.z, a1.w};
#pragma unroll
            for (int i = 0; i < 8; ++i) {
                ull a2 = pack2(am[i], am[i]);
                fma2(acc[i][0], a2, b01);
                fma2(acc[i][1], a2, b23);
            }
        }
        __syncthreads();
    }

#pragma unroll
    for (int i = 0; i < 8; ++i) {
        float2 p0 = unpack2(acc[i][0]);
        float2 p1 = unpack2(acc[i][1]);
        float4 o;
        o.x = p0.x + bias[0];
        o.y = p0.y + bias[1];
        o.z = p1.x + bias[2];
        o.w = p1.y + bias[3];
        size_t r = (size_t)(row0 + tm * 8 + i);
        *(float4*)&g_xg[r * G4H + col0 + tn * 4] = o;
    }
}

// ---------------------------------------------------------------------------
// Grid-wide sense-reversing barrier (all blocks resident: grid <= 148)
// ---------------------------------------------------------------------------
__device__ __forceinline__ void grid_sync(unsigned* mygen) {
    __syncthreads();
    if (threadIdx.x == 0) {
        unsigned g = *mygen;
        __threadfence();
        if (atomicAdd(&g_bar_cnt, 1u) == gridDim.x - 1) {
            atomicExch(&g_bar_cnt, 0u);
            __threadfence();
            atomicAdd(&g_bar_gen, 1u);
        } else {
            while (atomicAdd(&g_bar_gen, 0u) == g) { __nanosleep(64); }
            __threadfence();
        }
        *mygen = g + 1;
    }
    __syncthreads();
}

// ---------------------------------------------------------------------------
// Persistent recurrent scan. Grid = 128 blocks x 256 threads.
// Block b owns h-columns {2b, 2b+1} (=> 8 gate columns, c-state in registers).
// Each step: gates = xg[step] + h_prev @ Whh_slice^T, then LSTM cell,
// h written into `out` (which doubles as the h history), grid barrier.
// MB in {128, 256, 512}; RT = MB/128 rows per thread.
// ---------------------------------------------------------------------------
template <int MB>
__global__ void __launch_bounds__(256) scan_kernel(
    const float* __restrict__ Whh,   // [1024, 256] row-major
    float* __restrict__ out,         // [nsteps*MB, 256]
    int nsteps)
{
    constexpr int RT = MB / 128;
    __shared__ float Wsm[8 * 260];   // [gate*2+sub][k], padded stride 260

    const int tid     = threadIdx.x;
    const int warp    = tid >> 5;
    const int lane    = tid & 31;
    const int rowslot = lane & 15;   // 16 row slots per warp
    const int sub     = lane >> 4;   // which of the 2 owned h-columns
    const int c0      = blockIdx.x * 2;

    // Load W_hh slice: 8 rows (4 gates x 2 cols) x 256 k
    for (int idx = tid; idx < 8 * 64; idx += 256) {
        int rowi = idx >> 6;               // 0..7
        int k4   = (idx & 63) * 4;
        int g    = rowi >> 1, s = rowi & 1;
        float4 v = *(const float4*)&Whh[(size_t)(g * 256 + c0 + s) * HH + k4];
        *(float4*)&Wsm[rowi * 260 + k4] = v;
    }
    __syncthreads();

    unsigned mygen = 0;
    if (tid == 0) mygen = atomicAdd(&g_bar_gen, 0u);

    int rbase[RT];
#pragma unroll
    for (int i = 0; i < RT; ++i) rbase[i] = warp * (16 * RT) + i * 16 + rowslot;

    float c_reg[RT];
#pragma unroll
    for (int i = 0; i < RT; ++i) c_reg[i] = 0.f;

    for (int step = 0; step < nsteps; ++step) {
        ull acc[RT][4];
        // Seed accumulators with precomputed input gates (lo lane; hi = 0)
#pragma unroll
        for (int i = 0; i < RT; ++i) {
            size_t base = (size_t)(step * MB + rbase[i]) * G4H + c0 + sub;
#pragma unroll
            for (int g = 0; g < 4; ++g)
                acc[i][g] = (ull)__float_as_uint(g_xg[base + (size_t)g * 256]);
        }

        if (step > 0) {
            const float* hprev = out + (size_t)(step - 1) * MB * HH;
#pragma unroll 4
            for (int k4 = 0; k4 < 64; ++k4) {
                ulonglong2 w2[4];
#pragma unroll
                for (int g = 0; g < 4; ++g)
                    w2[g] = *(const ulonglong2*)&Wsm[(g * 2 + sub) * 260 + k4 * 4];
#pragma unroll
                for (int i = 0; i < RT; ++i) {
                    ulonglong2 h2 =
                        *(const ulonglong2*)&hprev[(size_t)rbase[i] * HH + k4 * 4];
#pragma unroll
                    for (int g = 0; g < 4; ++g) {
                        fma2(acc[i][g], h2.x, w2[g].x);
                        fma2(acc[i][g], h2.y, w2[g].y);
                    }
                }
            }
        }

        // LSTM cell + write h
        float* orow = out + (size_t)step * MB * HH;
#pragma unroll
        for (int i = 0; i < RT; ++i) {
            float2 pi = unpack2(acc[i][0]);
            float2 pf = unpack2(acc[i][1]);
            float2 pg = unpack2(acc[i][2]);
            float2 po = unpack2(acc[i][3]);
            float vi = pi.x + pi.y;
            float vf = pf.x + pf.y;
            float vg = pg.x + pg.y;
            float vo = po.x + po.y;
            float ig = sigf(vi);
            float fg = sigf(vf);
            float gt = tanh_fast(vg);
            float og = sigf(vo);
            float c  = fg * c_reg[i] + ig * gt;
            c_reg[i] = c;
            float h  = og * tanh_fast(c);
            orow[(size_t)rbase[i] * HH + c0 + sub] = h;
        }

        grid_sync(&mygen);
    }
}

// ---------------------------------------------------------------------------
// kernel_launch: 3 x (input GEMM -> persistent scan). Graph-capturable,
// allocation-free, deterministic.
// ---------------------------------------------------------------------------
extern "C" void kernel_launch(void* const* d_in, const int* in_sizes, int n_in,
                              void* d_out, int out_size)
{
    (void)in_sizes; (void)n_in; (void)out_size;
    const float* x    = (const float*)d_in[0];
    const float* Wih0 = (const float*)d_in[1];
    const float* Whh0 = (const float*)d_in[2];
    const float* bih0 = (const float*)d_in[3];
    const float* bhh0 = (const float*)d_in[4];
    const float* Wih1 = (const float*)d_in[5];
    const float* Whh1 = (const float*)d_in[6];
    const float* bih1 = (const float*)d_in[7];
    const float* bhh1 = (const float*)d_in[8];
    const float* Wih2 = (const float*)d_in[9];
    const float* Whh2 = (const float*)d_in[10];
    const float* bih2 = (const float*)d_in[11];
    const float* bhh2 = (const float*)d_in[12];
    float* out = (float*)d_out;

    float* tmp = nullptr;
    cudaGetSymbolAddress((void**)&tmp, g_tmp);

    dim3 ggrid(16, 1024);  // 64-col x 128-row tiles over [131072 x 1024]

    // Layer 0: rate 1, MB=128, 1024 steps, K=128
    gemm_xg_kernel<128><<<ggrid, 256>>>(x, Wih0, bih0, bhh0);
    scan_kernel<128><<<128, 256>>>(Whh0, tmp, 1024);

    // Layer 1: rate 2, MB=256, 512 steps, K=256
    gemm_xg_kernel<256><<<ggrid, 256>>>(tmp, Wih1, bih1, bhh1);
    scan_kernel<256><<<128, 256>>>(Whh1, tmp, 512);

    // Layer 2: rate 4, MB=512, 256 steps, K=256 (writes final output)
    gemm_xg_kernel<256><<<ggrid, 256>>>(tmp, Wih2, bih2, bhh2);
    scan_kernel<512><<<128, 256>>>(Whh2, out, 256);
}

// round 3
// speedup vs baseline: 1.4053x; 1.4053x over previous
#include <cuda_runtime.h>
#include <cstddef>

// Problem constants
#define TT   1024
#define BBATCH 128
#define DD   128
#define HH   256
#define RTOT (TT * BBATCH)   /* 131072 flat rows */
#define G4H  1024            /* 4*H gate columns */
#define SPAD 260             /* padded SMEM row stride (floats) */

typedef unsigned long long ull;

// ---------------------------------------------------------------------------
// Scratch (static device globals — no allocation APIs allowed)
// ---------------------------------------------------------------------------
__device__ float g_xg[(size_t)RTOT * G4H];   // 512 MB: per-layer input-gate staging
__device__ float g_tmp[(size_t)RTOT * HH];   // 128 MB: inter-layer activation buffer
__device__ unsigned g_bar_cnt = 0;
__device__ unsigned g_bar_gen = 0;

// ---------------------------------------------------------------------------
// f32x2 packed-FMA helpers (FFMA2: 2x FFMA-3reg throughput on sm_103a)
// ---------------------------------------------------------------------------
__device__ __forceinline__ void fma2(ull& d, ull a, ull b) {
    asm("fma.rn.f32x2 %0, %1, %2, %0;" : "+l"(d) : "l"(a), "l"(b));
}
__device__ __forceinline__ ull pack2(float lo, float hi) {
    ull r;
    asm("mov.b64 %0, {%1, %2};" : "=l"(r)
        : "r"(__float_as_uint(lo)), "r"(__float_as_uint(hi)));
    return r;
}
__device__ __forceinline__ float2 unpack2(ull v) {
    unsigned lo, hi;
    asm("mov.b64 {%0, %1}, %2;" : "=r"(lo), "=r"(hi) : "l"(v));
    return make_float2(__uint_as_float(lo), __uint_as_float(hi));
}
__device__ __forceinline__ unsigned ld_acq(const unsigned* p) {
    unsigned v;
    asm volatile("ld.acquire.gpu.u32 %0, [%1];" : "=r"(v) : "l"(p) : "memory");
    return v;
}

// Fast-but-accurate activations
__device__ __forceinline__ float sigf(float x) {
    return __fdividef(1.f, 1.f + __expf(-x));
}
__device__ __forceinline__ float tanh_fast(float x) {
    return 2.f * sigf(2.f * x) - 1.f;
}

// ---------------------------------------------------------------------------
// GEMM: g_xg[r][n] = sum_k A[r][k] * W[n][k] + bih[n] + bhh[n]
// (unchanged from R2 — known correct, ~5.5 ms total; tensor-core rewrite is
//  the next round's target)
// ---------------------------------------------------------------------------
template <int K>
__global__ void __launch_bounds__(256) gemm_xg_kernel(
    const float* __restrict__ A, const float* __restrict__ W,
    const float* __restrict__ bih, const float* __restrict__ bhh)
{
    __shared__ float Asm[16][132];
    __shared__ float Bsm[16][68];

    const int tid  = threadIdx.x;
    const int nb   = blockIdx.x;
    const int mb   = blockIdx.y;
    const int tm   = tid >> 4;
    const int tn   = tid & 15;
    const int row0 = mb * 128;
    const int col0 = nb * 64;

    float bias[4];
#pragma unroll
    for (int j = 0; j < 4; ++j)
        bias[j] = bih[col0 + tn * 4 + j] + bhh[col0 + tn * 4 + j];

    ull acc[8][2];
#pragma unroll
    for (int i = 0; i < 8; ++i) { acc[i][0] = 0ull; acc[i][1] = 0ull; }

    const int ar0 = tid >> 2;
    const int akv = (tid & 3) * 4;
    const int wn  = tid >> 2;
    const int wkv = (tid & 3) * 4;

    for (int k0 = 0; k0 < K; k0 += 16) {
#pragma unroll
        for (int h = 0; h < 2; ++h) {
            int r = ar0 + h * 64;
            float4 v = *(const float4*)&A[(size_t)(row0 + r) * K + k0 + akv];
            Asm[akv + 0][r] = v.x; Asm[akv + 1][r] = v.y;
            Asm[akv + 2][r] = v.z; Asm[akv + 3][r] = v.w;
        }
        {
            float4 v = *(const float4*)&W[(size_t)(col0 + wn) * K + k0 + wkv];
            Bsm[wkv + 0][wn] = v.x; Bsm[wkv + 1][wn] = v.y;
            Bsm[wkv + 2][wn] = v.z; Bsm[wkv + 3][wn] = v.w;
        }
        __syncthreads();

#pragma unroll
        for (int k = 0; k < 16; ++k) {
            float4 a0 = *(const float4*)&Asm[k][tm * 8];
            float4 a1 = *(const float4*)&Asm[k][tm * 8 + 4];
            float4 b  = *(const float4*)&Bsm[k][tn * 4];
            ull b01 = pack2(b.x, b.y);
            ull b23 = pack2(b.z, b.w);
            float am[8] = {a0.x, a0.y, a0.z, a0.w, a1.x, a1.y, a1.z, a1.w};
#pragma unroll
            for (int i = 0; i < 8; ++i) {
                ull a2 = pack2(am[i], am[i]);
                fma2(acc[i][0], a2, b01);
                fma2(acc[i][1], a2, b23);
            }
        }
        __syncthreads();
    }

#pragma unroll
    for (int i = 0; i < 8; ++i) {
        float2 p0 = unpack2(acc[i][0]);
        float2 p1 = unpack2(acc[i][1]);
        float4 o;
        o.x = p0.x + bias[0];
        o.y = p0.y + bias[1];
        o.z = p1.x + bias[2];
        o.w = p1.y + bias[3];
        size_t r = (size_t)(row0 + tm * 8 + i);
        *(float4*)&g_xg[r * G4H + col0 + tn * 4] = o;
    }
}

// ---------------------------------------------------------------------------
// Grid-wide sense-reversing barrier (all 128 blocks resident). Polling uses
// ld.acquire.gpu (no L2 atomic serialization on the hot path).
// ---------------------------------------------------------------------------
__device__ __forceinline__ void grid_sync(unsigned* mygen) {
    __syncthreads();
    if (threadIdx.x == 0) {
        unsigned g = *mygen;
        __threadfence();
        if (atomicAdd(&g_bar_cnt, 1u) == gridDim.x - 1) {
            atomicExch(&g_bar_cnt, 0u);
            __threadfence();
            atomicAdd(&g_bar_gen, 1u);
        } else {
            while (ld_acq(&g_bar_gen) == g) { __nanosleep(32); }
        }
        *mygen = g + 1;
    }
    __syncthreads();
}

// ---------------------------------------------------------------------------
// Persistent recurrent scan, 2-D ownership. Grid = 128 blocks x 256 threads.
// Block (cg, rg) owns CW h-columns [cg*CW, ...) x RW contiguous rows
// [rg*RW, ...). Each step:
//   1. cooperative COALESCED copy of the block's h_prev slab -> SMEM (padded)
//   2. each thread computes 4 gates for its (RPT rows x 1 col) from SMEM
//      using f32x2 over k-pairs; W slice resident in SMEM [gate][col][k]
//   3. LSTM cell, write h, grid barrier.
// Layouts chosen so every LDS phase is conflict-free (stride SPAD=260).
// ---------------------------------------------------------------------------
template <int MB, int CW, int RPT>
__global__ void __launch_bounds__(256, 1) scan_kernel(
    const float* __restrict__ Whh,   // [1024, 256] row-major
    float* __restrict__ out,         // [nsteps*MB, 256]
    int nsteps)
{
    constexpr int RPW = 256 / CW;        // threads per column = row slots
    constexpr int RW  = RPW * RPT;       // rows per block
    constexpr int NCG = 256 / CW;        // column groups

    extern __shared__ float smem[];
    float* Wsm = smem;                   // [4][CW][SPAD]
    float* Hsm = smem + 4 * CW * SPAD;   // [RW][SPAD]

    const int tid     = threadIdx.x;
    const int cg      = blockIdx.x % NCG;
    const int rg      = blockIdx.x / NCG;
    const int gc0     = cg * CW;
    const int rowbase = rg * RW;
    const int c       = tid / RPW;       // owned column (0..CW-1)
    const int q       = tid % RPW;       // row slot

    // Load W_hh slice once: Wsm[g][cc][k] = Whh[g*256 + gc0 + cc][k]
    for (int idx = tid; idx < 4 * CW * 64; idx += 256) {
        int k4 = idx % 64;
        int cc = (idx / 64) % CW;
        int g  = idx / (64 * CW);
        float4 v = *(const float4*)&Whh[(size_t)(g * 256 + gc0 + cc) * HH + k4 * 4];
        *(float4*)&Wsm[(g * CW + cc) * SPAD + k4 * 4] = v;
    }

    unsigned mygen = 0;
    if (tid == 0) mygen = ld_acq(&g_bar_gen);

    float c_st[RPT];
#pragma unroll
    for (int j = 0; j < RPT; ++j) c_st[j] = 0.f;

    __syncthreads();

    for (int step = 0; step < nsteps; ++step) {
        // Stage h_prev slab (contiguous RW*256 floats) into SMEM, coalesced.
        if (step > 0) {
            const float* hp = out + ((size_t)(step - 1) * MB + rowbase) * HH;
            for (int idx = tid; idx < RW * 64; idx += 256) {
                int r  = idx / 64;
                int k4 = idx % 64;
                float4 v = *(const float4*)&hp[r * HH + k4 * 4];
                *(float4*)&Hsm[r * SPAD + k4 * 4] = v;
            }
        }

        // Seed accumulators with precomputed input gates (lo lane of f32x2).
        ull acc[RPT][4];
#pragma unroll
        for (int j = 0; j < RPT; ++j) {
            int row = rowbase + q + j * RPW;
            size_t base = ((size_t)step * MB + row) * G4H + gc0 + c;
#pragma unroll
            for (int g = 0; g < 4; ++g)
                acc[j][g] = (ull)__float_as_uint(g_xg[base + (size_t)g * 256]);
        }

        __syncthreads();

        if (step > 0) {
#pragma unroll 2
            for (int k4 = 0; k4 < 64; ++k4) {
                ulonglong2 w[4];
#pragma unroll
                for (int g = 0; g < 4; ++g)
                    w[g] = *(const ulonglong2*)&Wsm[(g * CW + c) * SPAD + k4 * 4];
#pragma unroll
                for (int j = 0; j < RPT; ++j) {
                    ulonglong2 h2 =
                        *(const ulonglong2*)&Hsm[(q + j * RPW) * SPAD + k4 * 4];
#pragma unroll
                    for (int g = 0; g < 4; ++g) {
                        fma2(acc[j][g], h2.x, w[g].x);
                        fma2(acc[j][g], h2.y, w[g].y);
                    }
                }
            }
        }

        // LSTM cell + write h
        float* orow = out + (size_t)step * MB * HH;
#pragma unroll
        for (int j = 0; j < RPT; ++j) {
            float2 pi = unpack2(acc[j][0]);
            float2 pf = unpack2(acc[j][1]);
            float2 pg = unpack2(acc[j][2]);
            float2 po = unpack2(acc[j][3]);
            float vi = pi.x + pi.y;
            float vf = pf.x + pf.y;
            float vg = pg.x + pg.y;
            float vo = po.x + po.y;
            float ig = sigf(vi);
            float fg = sigf(vf);
            float gt = tanh_fast(vg);
            float og = sigf(vo);
            float cc2 = fg * c_st[j] + ig * gt;
            c_st[j] = cc2;
            float h = og * tanh_fast(cc2);
            orow[(size_t)(rowbase + q + j * RPW) * HH + gc0 + c] = h;
        }

        grid_sync(&mygen);
    }
}

// ---------------------------------------------------------------------------
// kernel_launch: 3 x (input GEMM -> persistent scan). Graph-capturable,
// allocation-free, deterministic.
// ---------------------------------------------------------------------------
extern "C" void kernel_launch(void* const* d_in, const int* in_sizes, int n_in,
                              void* d_out, int out_size)
{
    (void)in_sizes; (void)n_in; (void)out_size;
    const float* x    = (const float*)d_in[0];
    const float* Wih0 = (const float*)d_in[1];
    const float* Whh0 = (const float*)d_in[2];
    const float* bih0 = (const float*)d_in[3];
    const float* bhh0 = (const float*)d_in[4];
    const float* Wih1 = (const float*)d_in[5];
    const float* Whh1 = (const float*)d_in[6];
    const float* bih1 = (const float*)d_in[7];
    const float* bhh1 = (const float*)d_in[8];
    const float* Wih2 = (const float*)d_in[9];
    const float* Whh2 = (const float*)d_in[10];
    const float* bih2 = (const float*)d_in[11];
    const float* bhh2 = (const float*)d_in[12];
    float* out = (float*)d_out;

    float* tmp = nullptr;
    cudaGetSymbolAddress((void**)&tmp, g_tmp);

    // Dynamic SMEM sizes per scan instantiation
    // scan<128,16,1>: (4*16 + 16) * SPAD floats
    // scan<256,32,2>: (4*32 + 16) * SPAD floats
    // scan<512,32,4>: (4*32 + 32) * SPAD floats
    const int smem0 = (4 * 16 + 16) * SPAD * 4;   //  83200 B
    const int smem1 = (4 * 32 + 16) * SPAD * 4;   // 149760 B
    const int smem2 = (4 * 32 + 32) * SPAD * 4;   // 166400 B
    cudaFuncSetAttribute((const void*)scan_kernel<128, 16, 1>,
                         cudaFuncAttributeMaxDynamicSharedMemorySize, smem0);
    cudaFuncSetAttribute((const void*)scan_kernel<256, 32, 2>,
                         cudaFuncAttributeMaxDynamicSharedMemorySize, smem1);
    cudaFuncSetAttribute((const void*)scan_kernel<512, 32, 4>,
                         cudaFuncAttributeMaxDynamicSharedMemorySize, smem2);

    dim3 ggrid(16, 1024);  // 64-col x 128-row tiles over [131072 x 1024]

    // Layer 0: rate 1, MB=128, 1024 steps, K=128
    gemm_xg_kernel<128><<<ggrid, 256>>>(x, Wih0, bih0, bhh0);
    scan_kernel<128, 16, 1><<<128, 256, smem0>>>(Whh0, tmp, 1024);

    // Layer 1: rate 2, MB=256, 512 steps, K=256
    gemm_xg_kernel<256><<<ggrid, 256>>>(tmp, Wih1, bih1, bhh1);
    scan_kernel<256, 32, 2><<<128, 256, smem1>>>(Whh1, tmp, 512);

    // Layer 2: rate 4, MB=512, 256 steps, K=256 (writes final output)
    gemm_xg_kernel<256><<<ggrid, 256>>>(tmp, Wih2, bih2, bhh2);
    scan_kernel<512, 32, 4><<<128, 256, smem2>>>(Whh2, out, 256);
}

// round 5
// speedup vs baseline: 2.4334x; 1.7316x over previous
#include <cuda_runtime.h>
#include <cuda_bf16.h>
#include <cstddef>
#include <cstdint>

// Problem constants
#define TT     1024
#define BBATCH 128
#define DD     128
#define HH     256
#define RTOT   (TT * BBATCH)   /* 131072 flat rows */
#define G4H    1024            /* 4*H gate columns */
#define SPAD   260             /* padded SMEM row stride (floats) */
#define BKC    64              /* GEMM K chunk in bf16 elements (128B rows) */

typedef unsigned long long ull;

// ---------------------------------------------------------------------------
// Scratch (static device globals — no allocation APIs allowed)
// g_xg layout is PERMUTED for scan-side coalescing:
//   element (flat row r, gate col n) lives at ((n>>4)*RTOT + r)*16 + (n&15)
// ---------------------------------------------------------------------------
__device__ float g_xg[(size_t)RTOT * G4H];   // 512 MB gate staging (permuted)
__device__ float g_tmp[(size_t)RTOT * HH];   // 128 MB inter-layer activations
__device__ __align__(256) __nv_bfloat16 g_Ah[(size_t)RTOT * HH]; // 64 MB
__device__ __align__(256) __nv_bfloat16 g_Al[(size_t)RTOT * HH]; // 64 MB
__device__ __align__(256) __nv_bfloat16 g_Wh[1024 * HH];
__device__ __align__(256) __nv_bfloat16 g_Wl[1024 * HH];
__device__ unsigned g_bar_cnt = 0;
__device__ unsigned g_bar_gen = 0;

// ---------------------------------------------------------------------------
// Helpers (portable PTX only: works for compute_103 generic target)
// ---------------------------------------------------------------------------
__device__ __forceinline__ void fma2(ull& d, ull a, ull b) {
    asm("fma.rn.f32x2 %0, %1, %2, %0;" : "+l"(d) : "l"(a), "l"(b));
}
__device__ __forceinline__ float2 unpack2(ull v) {
    unsigned lo, hi;
    asm("mov.b64 {%0, %1}, %2;" : "=r"(lo), "=r"(hi) : "l"(v));
    return make_float2(__uint_as_float(lo), __uint_as_float(hi));
}
__device__ __forceinline__ unsigned ld_acq(const unsigned* p) {
    unsigned v;
    asm volatile("ld.acquire.gpu.u32 %0, [%1];" : "=r"(v) : "l"(p) : "memory");
    return v;
}
__device__ __forceinline__ float sigf(float x) {
    return __fdividef(1.f, 1.f + __expf(-x));
}
__device__ __forceinline__ float tanh_fast(float x) {
    return 2.f * sigf(2.f * x) - 1.f;
}
__device__ __forceinline__ uint32_t smem_u32(const void* p) {
    uint32_t a;
    asm("{ .reg .u64 t; cvta.to.shared.u64 t, %1; cvt.u32.u64 %0, t; }"
        : "=r"(a) : "l"(p));
    return a;
}
#define SWZ(o) ((o) ^ (((o) >> 3) & 0x70))
__device__ __forceinline__ void cp16(uint32_t dst, const void* src) {
    asm volatile("cp.async.cg.shared.global [%0], [%1], 16;"
                 :: "r"(dst), "l"(src) : "memory");
}
__device__ __forceinline__ void ldm4(uint32_t* r, uint32_t addr) {
    asm volatile("ldmatrix.sync.aligned.m8n8.x4.shared.b16 {%0,%1,%2,%3}, [%4];"
                 : "=r"(r[0]), "=r"(r[1]), "=r"(r[2]), "=r"(r[3]) : "r"(addr));
}
__device__ __forceinline__ void mma_bf16(float* d, const uint32_t* a,
                                         const uint32_t* b) {
    asm volatile(
        "mma.sync.aligned.m16n8k16.row.col.f32.bf16.bf16.f32 "
        "{%0,%1,%2,%3}, {%4,%5,%6,%7}, {%8,%9}, {%0,%1,%2,%3};"
        : "+f"(d[0]), "+f"(d[1]), "+f"(d[2]), "+f"(d[3])
        : "r"(a[0]), "r"(a[1]), "r"(a[2]), "r"(a[3]), "r"(b[0]), "r"(b[1]));
}

// ---------------------------------------------------------------------------
// Split-conversion: fp32 -> (bf16 hi, bf16 lo). n4 = element count / 4.
// ---------------------------------------------------------------------------
__global__ void __launch_bounds__(256) convert_split_kernel(
    const float* __restrict__ src, __nv_bfloat16* __restrict__ hi,
    __nv_bfloat16* __restrict__ lo, int n4)
{
    int i = blockIdx.x * blockDim.x + threadIdx.x;
    if (i >= n4) return;
    float4 v = ((const float4*)src)[i];
    __nv_bfloat16 h0 = __float2bfloat16(v.x);
    __nv_bfloat16 h1 = __float2bfloat16(v.y);
    __nv_bfloat16 h2 = __float2bfloat16(v.z);
    __nv_bfloat16 h3 = __float2bfloat16(v.w);
    __nv_bfloat16 l0 = __float2bfloat16(v.x - __bfloat162float(h0));
    __nv_bfloat16 l1 = __float2bfloat16(v.y - __bfloat162float(h1));
    __nv_bfloat16 l2 = __float2bfloat16(v.z - __bfloat162float(h2));
    __nv_bfloat16 l3 = __float2bfloat16(v.w - __bfloat162float(h3));
    ((__nv_bfloat162*)hi)[2 * i]     = __nv_bfloat162(h0, h1);
    ((__nv_bfloat162*)hi)[2 * i + 1] = __nv_bfloat162(h2, h3);
    ((__nv_bfloat162*)lo)[2 * i]     = __nv_bfloat162(l0, l1);
    ((__nv_bfloat162*)lo)[2 * i + 1] = __nv_bfloat162(l2, l3);
}

// ---------------------------------------------------------------------------
// HMMA bf16-split GEMM: xg[r][n] = sum_k A[r][k]*W[n][k] + bih[n]+bhh[n]
// Block tile 128(M) x 128(N), K chunk 64 (bf16, 128B SW rows), 8 warps in a
// 2(M) x 4(N) grid, each warp 64x32 via 4x4 mma.m16n8k16 tiles.
// Three passes (Ah,Wh),(Al,Wh),(Ah,Wl) accumulate in the same fp32 registers.
// Output written in the PERMUTED g_xg layout.
// ---------------------------------------------------------------------------
template <int K>
__global__ void __launch_bounds__(256) gemm_hmma_kernel(
    const float* __restrict__ bih, const float* __restrict__ bhh)
{
    extern __shared__ char smem[];
    const uint32_t abase = (smem_u32(smem) + 1023u) & ~1023u;

    const int tid  = threadIdx.x;
    const int wid  = tid >> 5;
    const int lane = tid & 31;
    const int col0 = blockIdx.x * 128;
    const int row0 = blockIdx.y * 128;
    const int wm   = wid & 1;           // M half (64 rows)
    const int wn   = wid >> 1;          // N quarter (32 cols)

    const __nv_bfloat16* Aop[3] = {g_Ah, g_Al, g_Ah};
    const __nv_bfloat16* Bop[3] = {g_Wh, g_Wh, g_Wl};
    constexpr int KCH = K / BKC;
    constexpr int NC  = 3 * KCH;

    auto prefetch = [&](int c) {
        const int pass = c / KCH;
        const int kc   = c % KCH;
        const __nv_bfloat16* A = Aop[pass];
        const __nv_bfloat16* B = Bop[pass];
        const uint32_t bufA = abase + (uint32_t)(c & 1) * 32768u;
        const uint32_t bufB = bufA + 16384u;
#pragma unroll
        for (int i = 0; i < 4; ++i) {
            int ch = tid + i * 256;
            int r  = ch >> 3;           // 0..127
            int cc = ch & 7;            // 16B column within 128B row
            uint32_t off = SWZ((uint32_t)(r * 128 + cc * 16));
            cp16(bufA + off, A + (size_t)(row0 + r) * K + kc * BKC + cc * 8);
            cp16(bufB + off, B + (size_t)(col0 + r) * K + kc * BKC + cc * 8);
        }
        asm volatile("cp.async.commit_group;" ::: "memory");
    };

    float acc[4][4][4];
#pragma unroll
    for (int mt = 0; mt < 4; ++mt)
#pragma unroll
        for (int nt = 0; nt < 4; ++nt)
#pragma unroll
            for (int i = 0; i < 4; ++i) acc[mt][nt][i] = 0.f;

    prefetch(0);

    for (int c = 0; c < NC; ++c) {
        if (c + 1 < NC) {
            prefetch(c + 1);
            asm volatile("cp.async.wait_group 1;" ::: "memory");
        } else {
            asm volatile("cp.async.wait_group 0;" ::: "memory");
        }
        __syncthreads();

        const uint32_t bufA = abase + (uint32_t)(c & 1) * 32768u;
        const uint32_t bufB = bufA + 16384u;

#pragma unroll
        for (int ks = 0; ks < 4; ++ks) {           // 4 x k16 within chunk
            uint32_t afr[4][4];
            {
                int arow = wm * 64 + (lane & 15);
                int kb   = ks * 32 + (lane >> 4) * 16;
#pragma unroll
                for (int mt = 0; mt < 4; ++mt)
                    ldm4(afr[mt],
                         bufA + SWZ((uint32_t)((arow + mt * 16) * 128 + kb)));
            }
            uint32_t bfr[4][2];
            {
                int j    = lane >> 3;              // 0..3
                int brow = (j >> 1) * 8 + (lane & 7);
                int kb   = ks * 32 + (j & 1) * 16;
#pragma unroll
                for (int p = 0; p < 2; ++p) {
                    uint32_t r[4];
                    ldm4(r, bufB +
                            SWZ((uint32_t)((wn * 32 + p * 16 + brow) * 128 + kb)));
                    bfr[p * 2][0]     = r[0];
                    bfr[p * 2][1]     = r[1];
                    bfr[p * 2 + 1][0] = r[2];
                    bfr[p * 2 + 1][1] = r[3];
                }
            }
#pragma unroll
            for (int mt = 0; mt < 4; ++mt)
#pragma unroll
                for (int nt = 0; nt < 4; ++nt)
                    mma_bf16(acc[mt][nt], afr[mt], bfr[nt]);
        }
        __syncthreads();   // protect buffer (c&1) from prefetch(c+2)
    }

    // Epilogue: bias + store to permuted g_xg. n>>4 indexes the 16-col plane.
#pragma unroll
    for (int nt = 0; nt < 4; ++nt) {
        int n0 = col0 + wn * 32 + nt * 8 + (lane & 3) * 2;
        float b0 = bih[n0] + bhh[n0];
        float b1 = bih[n0 + 1] + bhh[n0 + 1];
        size_t plane = (size_t)(n0 >> 4) * RTOT;
        int cc = n0 & 15;
#pragma unroll
        for (int mt = 0; mt < 4; ++mt) {
            int r0 = row0 + wm * 64 + mt * 16 + (lane >> 2);
            float2 v0 = make_float2(acc[mt][nt][0] + b0, acc[mt][nt][1] + b1);
            float2 v1 = make_float2(acc[mt][nt][2] + b0, acc[mt][nt][3] + b1);
            *(float2*)&g_xg[(plane + r0) * 16 + cc]     = v0;
            *(float2*)&g_xg[(plane + r0 + 8) * 16 + cc] = v1;
        }
    }
}

// ---------------------------------------------------------------------------
// Grid-wide sense-reversing barrier (all 128 blocks resident).
// ---------------------------------------------------------------------------
__device__ __forceinline__ void grid_sync(unsigned* mygen) {
    __syncthreads();
    if (threadIdx.x == 0) {
        unsigned g = *mygen;
        __threadfence();
        if (atomicAdd(&g_bar_cnt, 1u) == gridDim.x - 1) {
            atomicExch(&g_bar_cnt, 0u);
            __threadfence();
            atomicAdd(&g_bar_gen, 1u);
        } else {
            while (ld_acq(&g_bar_gen) == g) { __nanosleep(32); }
        }
        *mygen = g + 1;
    }
    __syncthreads();
}

// ---------------------------------------------------------------------------
// Persistent recurrent scan, 2-D ownership + fully-coalesced gmem traffic.
// Block (cg, rg) owns CW h-columns x RW contiguous rows. Per step:
//   1. coalesced copy h_prev slab -> Hsm, xg seed slabs (permuted) -> Xsm
//   2. gates = seeds + h_prev @ Whh^T from SMEM (f32x2), LSTM cell
//   3. h staged to Ssm -> coalesced float4 STG; grid barrier.
// CWP padding makes Xsm/Ssm thread-access conflict-free.
// ---------------------------------------------------------------------------
template <int MB, int CW, int RPT>
__global__ void __launch_bounds__(256, 1) scan_kernel(
    const float* __restrict__ Whh,   // [1024, 256] row-major
    float* __restrict__ out,         // [nsteps*MB, 256]
    int nsteps)
{
    constexpr int RPW = 256 / CW;        // row slots per column
    constexpr int RW  = RPW * RPT;       // rows per block
    constexpr int NCG = 256 / CW;        // column groups
    constexpr int CWP = (CW == 16) ? 18 : 36;  // conflict-free padded stride
    constexpr int NSL = CW / 16;         // 16-col planes per block

    extern __shared__ float smemf[];
    float* Wsm = smemf;                          // [4*CW][SPAD]
    float* Hsm = Wsm + 4 * CW * SPAD;            // [RW][SPAD]
    float* Xsm = Hsm + RW * SPAD;                // [4*RW][CWP]
    float* Ssm = Xsm + 4 * RW * CWP;             // [RW][CWP]

    const int tid     = threadIdx.x;
    const int cg      = blockIdx.x % NCG;
    const int rg      = blockIdx.x / NCG;
    const int gc0     = cg * CW;
    const int rowbase = rg * RW;
    const int c       = tid / RPW;       // owned column (0..CW-1)
    const int q       = tid % RPW;       // row slot

    for (int idx = tid; idx < 4 * CW * 64; idx += 256) {
        int k4 = idx % 64;
        int cc = (idx / 64) % CW;
        int g  = idx / (64 * CW);
        float4 v = *(const float4*)&Whh[(size_t)(g * 256 + gc0 + cc) * HH + k4 * 4];
        *(float4*)&Wsm[(g * CW + cc) * SPAD + k4 * 4] = v;
    }

    unsigned mygen = 0;
    if (tid == 0) mygen = ld_acq(&g_bar_gen);

    float c_st[RPT];
#pragma unroll
    for (int j = 0; j < RPT; ++j) c_st[j] = 0.f;

    __syncthreads();

    for (int step = 0; step < nsteps; ++step) {
        // --- stage h_prev slab (coalesced) ---
        if (step > 0) {
            const float* hp = out + ((size_t)(step - 1) * MB + rowbase) * HH;
            for (int idx = tid; idx < RW * 64; idx += 256) {
                int r  = idx / 64;
                int k4 = idx % 64;
                float4 v = *(const float4*)&hp[r * HH + k4 * 4];
                *(float4*)&Hsm[r * SPAD + k4 * 4] = v;
            }
        }
        // --- stage xg seeds from permuted layout (fully contiguous slabs) ---
        {
            const size_t srow0 = (size_t)step * MB + rowbase;
            for (int idx = tid; idx < 4 * NSL * RW * 4; idx += 256) {
                int c4   = idx & 3;
                int r    = (idx >> 2) % RW;
                int rest = idx / (4 * RW);
                int cgi  = rest % NSL;
                int g    = rest / NSL;
                const float* src =
                    &g_xg[((size_t)(g * 16 + cg * NSL + cgi) * RTOT + srow0 + r) * 16
                          + c4 * 4];
                float4 v = *(const float4*)src;
                float* dst = &Xsm[(g * RW + r) * CWP + cgi * 16 + c4 * 4];
                dst[0] = v.x; dst[1] = v.y; dst[2] = v.z; dst[3] = v.w;
            }
        }
        __syncthreads();

        ull acc[RPT][4];
#pragma unroll
        for (int j = 0; j < RPT; ++j)
#pragma unroll
            for (int g = 0; g < 4; ++g)
                acc[j][g] =
                    (ull)__float_as_uint(Xsm[(g * RW + q + j * RPW) * CWP + c]);

        if (step > 0) {
#pragma unroll 2
            for (int k4 = 0; k4 < 64; ++k4) {
                ulonglong2 w[4];
#pragma unroll
                for (int g = 0; g < 4; ++g)
                    w[g] = *(const ulonglong2*)&Wsm[(g * CW + c) * SPAD + k4 * 4];
#pragma unroll
                for (int j = 0; j < RPT; ++j) {
                    ulonglong2 h2 =
                        *(const ulonglong2*)&Hsm[(q + j * RPW) * SPAD + k4 * 4];
#pragma unroll
                    for (int g = 0; g < 4; ++g) {
                        fma2(acc[j][g], h2.x, w[g].x);
                        fma2(acc[j][g], h2.y, w[g].y);
                    }
                }
            }
        }

        // LSTM cell -> stage h into Ssm
#pragma unroll
        for (int j = 0; j < RPT; ++j) {
            float2 pi = unpack2(acc[j][0]);
            float2 pf = unpack2(acc[j][1]);
            float2 pg = unpack2(acc[j][2]);
            float2 po = unpack2(acc[j][3]);
            float vi = pi.x + pi.y;
            float vf = pf.x + pf.y;
            float vg = pg.x + pg.y;
            float vo = po.x + po.y;
            float ig = sigf(vi);
            float fg = sigf(vf);
            float gt = tanh_fast(vg);
            float og = sigf(vo);
            float cc2 = fg * c_st[j] + ig * gt;
            c_st[j] = cc2;
            Ssm[(q + j * RPW) * CWP + c] = og * tanh_fast(cc2);
        }
        __syncthreads();

        // --- coalesced h store ---
        {
            float* orow = out + ((size_t)step * MB + rowbase) * HH + gc0;
            for (int idx = tid; idx < RW * (CW / 4); idx += 256) {
                int c4 = idx % (CW / 4);
                int r  = idx / (CW / 4);
                const float* s = &Ssm[r * CWP + c4 * 4];
                float4 v = make_float4(s[0], s[1], s[2], s[3]);
                *(float4*)&orow[(size_t)r * HH + c4 * 4] = v;
            }
        }

        grid_sync(&mygen);
    }
}

// ---------------------------------------------------------------------------
// kernel_launch: per layer: split-convert A & W -> HMMA GEMM -> scan.
// Graph-capturable, allocation-free, deterministic.
// ---------------------------------------------------------------------------
extern "C" void kernel_launch(void* const* d_in, const int* in_sizes, int n_in,
                              void* d_out, int out_size)
{
    (void)in_sizes; (void)n_in; (void)out_size;
    const float* x    = (const float*)d_in[0];
    const float* Wih0 = (const float*)d_in[1];
    const float* Whh0 = (const float*)d_in[2];
    const float* bih0 = (const float*)d_in[3];
    const float* bhh0 = (const float*)d_in[4];
    const float* Wih1 = (const float*)d_in[5];
    const float* Whh1 = (const float*)d_in[6];
    const float* bih1 = (const float*)d_in[7];
    const float* bhh1 = (const float*)d_in[8];
    const float* Wih2 = (const float*)d_in[9];
    const float* Whh2 = (const float*)d_in[10];
    const float* bih2 = (const float*)d_in[11];
    const float* bhh2 = (const float*)d_in[12];
    float* out = (float*)d_out;

    float* tmp = nullptr;
    cudaGetSymbolAddress((void**)&tmp, g_tmp);
    __nv_bfloat16 *Ah = nullptr, *Al = nullptr, *Wh = nullptr, *Wl = nullptr;
    cudaGetSymbolAddress((void**)&Ah, g_Ah);
    cudaGetSymbolAddress((void**)&Al, g_Al);
    cudaGetSymbolAddress((void**)&Wh, g_Wh);
    cudaGetSymbolAddress((void**)&Wl, g_Wl);

    // Scan SMEM sizes: (4*CW + RW)*SPAD + 5*RW*CWP floats
    const int smem0 = ((4 * 16 + 16) * SPAD + 5 * 16 * 18) * 4;   //  88960 B
    const int smem1 = ((4 * 32 + 16) * SPAD + 5 * 16 * 36) * 4;   // 161280 B
    const int smem2 = ((4 * 32 + 32) * SPAD + 5 * 32 * 36) * 4;   // 189440 B
    cudaFuncSetAttribute((const void*)scan_kernel<128, 16, 1>,
                         cudaFuncAttributeMaxDynamicSharedMemorySize, smem0);
    cudaFuncSetAttribute((const void*)scan_kernel<256, 32, 2>,
                         cudaFuncAttributeMaxDynamicSharedMemorySize, smem1);
    cudaFuncSetAttribute((const void*)scan_kernel<512, 32, 4>,
                         cudaFuncAttributeMaxDynamicSharedMemorySize, smem2);

    const int gsm = 1024 + 2 * 32768;   // align pad + double-buffered tiles
    cudaFuncSetAttribute((const void*)gemm_hmma_kernel<128>,
                         cudaFuncAttributeMaxDynamicSharedMemorySize, gsm);
    cudaFuncSetAttribute((const void*)gemm_hmma_kernel<256>,
                         cudaFuncAttributeMaxDynamicSharedMemorySize, gsm);

    dim3 ggrid(8, 1024);   // 128-col x 128-row tiles over [131072 x 1024]

    // ---- Layer 0: K=128, MB=128, 1024 steps
    {
        int n4a = RTOT * 128 / 4;
        convert_split_kernel<<<(n4a + 255) / 256, 256>>>(x, Ah, Al, n4a);
        int n4w = 1024 * 128 / 4;
        convert_split_kernel<<<(n4w + 255) / 256, 256>>>(Wih0, Wh, Wl, n4w);
        gemm_hmma_kernel<128><<<ggrid, 256, gsm>>>(bih0, bhh0);
        scan_kernel<128, 16, 1><<<128, 256, smem0>>>(Whh0, tmp, 1024);
    }
    // ---- Layer 1: K=256, MB=256, 512 steps
    {
        int n4a = RTOT * 256 / 4;
        convert_split_kernel<<<(n4a + 255) / 256, 256>>>(tmp, Ah, Al, n4a);
        int n4w = 1024 * 256 / 4;
        convert_split_kernel<<<(n4w + 255) / 256, 256>>>(Wih1, Wh, Wl, n4w);
        gemm_hmma_kernel<256><<<ggrid, 256, gsm>>>(bih1, bhh1);
        scan_kernel<256, 32, 2><<<128, 256, smem1>>>(Whh1, tmp, 512);
    }
    // ---- Layer 2: K=256, MB=512, 256 steps (writes final output)
    {
        int n4a = RTOT * 256 / 4;
        convert_split_kernel<<<(n4a + 255) / 256, 256>>>(tmp, Ah, Al, n4a);
        int n4w = 1024 * 256 / 4;
        convert_split_kernel<<<(n4w + 255) / 256, 256>>>(Wih2, Wh, Wl, n4w);
        gemm_hmma_kernel<256><<<ggrid, 256, gsm>>>(bih2, bhh2);
        scan_kernel<512, 32, 4><<<128, 256, smem2>>>(Whh2, out, 256);
    }
}

// round 6
// speedup vs baseline: 2.6278x; 1.0799x over previous
#include <cuda_runtime.h>
#include <cuda_bf16.h>
#include <cstddef>
#include <cstdint>

// Problem constants
#define TT     1024
#define BBATCH 128
#define DD     128
#define HH     256
#define RTOT   (TT * BBATCH)   /* 131072 flat rows */
#define G4H    1024            /* 4*H gate columns */
#define SPAD   260             /* padded SMEM row stride (floats) */
#define BKC    64              /* GEMM K chunk in bf16 elements (128B rows) */

typedef unsigned long long ull;

// ---------------------------------------------------------------------------
// Scratch (static device globals — no allocation APIs allowed)
// g_xg layout is PERMUTED for scan-side coalescing:
//   element (flat row r, gate col n) lives at ((n>>4)*RTOT + r)*16 + (n&15)
// ---------------------------------------------------------------------------
__device__ float g_xg[(size_t)RTOT * G4H];   // 512 MB gate staging (permuted)
__device__ float g_tmp[(size_t)RTOT * HH];   // 128 MB inter-layer activations
__device__ __align__(256) __nv_bfloat16 g_Ah[(size_t)RTOT * HH]; // 64 MB
__device__ __align__(256) __nv_bfloat16 g_Al[(size_t)RTOT * HH]; // 64 MB
__device__ __align__(256) __nv_bfloat16 g_Wh[1024 * HH];
__device__ __align__(256) __nv_bfloat16 g_Wl[1024 * HH];
// Per-row-group barrier state: [rg*64+0] = cnt, [rg*64+32] = gen (separate
// 128B lines so gen-polling never contends with cnt atomics). Sense-relative
// (base read per launch) + cnt self-resets => deterministic across replays.
__device__ __align__(128) unsigned g_rgbar[16 * 64];

// ---------------------------------------------------------------------------
// Helpers (portable PTX only: works for compute_103 generic target)
// ---------------------------------------------------------------------------
__device__ __forceinline__ void fma2(ull& d, ull a, ull b) {
    asm("fma.rn.f32x2 %0, %1, %2, %0;" : "+l"(d) : "l"(a), "l"(b));
}
__device__ __forceinline__ float2 unpack2(ull v) {
    unsigned lo, hi;
    asm("mov.b64 {%0, %1}, %2;" : "=r"(lo), "=r"(hi) : "l"(v));
    return make_float2(__uint_as_float(lo), __uint_as_float(hi));
}
__device__ __forceinline__ unsigned ld_acq(const unsigned* p) {
    unsigned v;
    asm volatile("ld.acquire.gpu.u32 %0, [%1];" : "=r"(v) : "l"(p) : "memory");
    return v;
}
__device__ __forceinline__ float sigf(float x) {
    return __fdividef(1.f, 1.f + __expf(-x));
}
__device__ __forceinline__ float tanh_fast(float x) {
    return 2.f * sigf(2.f * x) - 1.f;
}
__device__ __forceinline__ uint32_t smem_u32(const void* p) {
    uint32_t a;
    asm("{ .reg .u64 t; cvta.to.shared.u64 t, %1; cvt.u32.u64 %0, t; }"
        : "=r"(a) : "l"(p));
    return a;
}
#define SWZ(o) ((o) ^ (((o) >> 3) & 0x70))
__device__ __forceinline__ void cp16(uint32_t dst, const void* src) {
    asm volatile("cp.async.cg.shared.global [%0], [%1], 16;"
                 :: "r"(dst), "l"(src) : "memory");
}
__device__ __forceinline__ void ldm4(uint32_t* r, uint32_t addr) {
    asm volatile("ldmatrix.sync.aligned.m8n8.x4.shared.b16 {%0,%1,%2,%3}, [%4];"
                 : "=r"(r[0]), "=r"(r[1]), "=r"(r[2]), "=r"(r[3]) : "r"(addr));
}
__device__ __forceinline__ void mma_bf16(float* d, const uint32_t* a,
                                         const uint32_t* b) {
    asm volatile(
        "mma.sync.aligned.m16n8k16.row.col.f32.bf16.bf16.f32 "
        "{%0,%1,%2,%3}, {%4,%5,%6,%7}, {%8,%9}, {%0,%1,%2,%3};"
        : "+f"(d[0]), "+f"(d[1]), "+f"(d[2]), "+f"(d[3])
        : "r"(a[0]), "r"(a[1]), "r"(a[2]), "r"(a[3]), "r"(b[0]), "r"(b[1]));
}

// ---------------------------------------------------------------------------
// Split-conversion: fp32 -> (bf16 hi, bf16 lo). n4 = element count / 4.
// ---------------------------------------------------------------------------
__global__ void __launch_bounds__(256) convert_split_kernel(
    const float* __restrict__ src, __nv_bfloat16* __restrict__ hi,
    __nv_bfloat16* __restrict__ lo, int n4)
{
    int i = blockIdx.x * blockDim.x + threadIdx.x;
    if (i >= n4) return;
    float4 v = ((const float4*)src)[i];
    __nv_bfloat16 h0 = __float2bfloat16(v.x);
    __nv_bfloat16 h1 = __float2bfloat16(v.y);
    __nv_bfloat16 h2 = __float2bfloat16(v.z);
    __nv_bfloat16 h3 = __float2bfloat16(v.w);
    __nv_bfloat16 l0 = __float2bfloat16(v.x - __bfloat162float(h0));
    __nv_bfloat16 l1 = __float2bfloat16(v.y - __bfloat162float(h1));
    __nv_bfloat16 l2 = __float2bfloat16(v.z - __bfloat162float(h2));
    __nv_bfloat16 l3 = __float2bfloat16(v.w - __bfloat162float(h3));
    ((__nv_bfloat162*)hi)[2 * i]     = __nv_bfloat162(h0, h1);
    ((__nv_bfloat162*)hi)[2 * i + 1] = __nv_bfloat162(h2, h3);
    ((__nv_bfloat162*)lo)[2 * i]     = __nv_bfloat162(l0, l1);
    ((__nv_bfloat162*)lo)[2 * i + 1] = __nv_bfloat162(l2, l3);
}

// ---------------------------------------------------------------------------
// HMMA bf16-split GEMM (unchanged from R5 — proven).
// xg[r][n] = sum_k A[r][k]*W[n][k] + bih[n]+bhh[n], output PERMUTED.
// ---------------------------------------------------------------------------
template <int K>
__global__ void __launch_bounds__(256) gemm_hmma_kernel(
    const float* __restrict__ bih, const float* __restrict__ bhh)
{
    extern __shared__ char smem[];
    const uint32_t abase = (smem_u32(smem) + 1023u) & ~1023u;

    const int tid  = threadIdx.x;
    const int wid  = tid >> 5;
    const int lane = tid & 31;
    const int col0 = blockIdx.x * 128;
    const int row0 = blockIdx.y * 128;
    const int wm   = wid & 1;
    const int wn   = wid >> 1;

    const __nv_bfloat16* Aop[3] = {g_Ah, g_Al, g_Ah};
    const __nv_bfloat16* Bop[3] = {g_Wh, g_Wh, g_Wl};
    constexpr int KCH = K / BKC;
    constexpr int NC  = 3 * KCH;

    auto prefetch = [&](int c) {
        const int pass = c / KCH;
        const int kc   = c % KCH;
        const __nv_bfloat16* A = Aop[pass];
        const __nv_bfloat16* B = Bop[pass];
        const uint32_t bufA = abase + (uint32_t)(c & 1) * 32768u;
        const uint32_t bufB = bufA + 16384u;
#pragma unroll
        for (int i = 0; i < 4; ++i) {
            int ch = tid + i * 256;
            int r  = ch >> 3;
            int cc = ch & 7;
            uint32_t off = SWZ((uint32_t)(r * 128 + cc * 16));
            cp16(bufA + off, A + (size_t)(row0 + r) * K + kc * BKC + cc * 8);
            cp16(bufB + off, B + (size_t)(col0 + r) * K + kc * BKC + cc * 8);
        }
        asm volatile("cp.async.commit_group;" ::: "memory");
    };

    float acc[4][4][4];
#pragma unroll
    for (int mt = 0; mt < 4; ++mt)
#pragma unroll
        for (int nt = 0; nt < 4; ++nt)
#pragma unroll
            for (int i = 0; i < 4; ++i) acc[mt][nt][i] = 0.f;

    prefetch(0);

    for (int c = 0; c < NC; ++c) {
        if (c + 1 < NC) {
            prefetch(c + 1);
            asm volatile("cp.async.wait_group 1;" ::: "memory");
        } else {
            asm volatile("cp.async.wait_group 0;" ::: "memory");
        }
        __syncthreads();

        const uint32_t bufA = abase + (uint32_t)(c & 1) * 32768u;
        const uint32_t bufB = bufA + 16384u;

#pragma unroll
        for (int ks = 0; ks < 4; ++ks) {
            uint32_t afr[4][4];
            {
                int arow = wm * 64 + (lane & 15);
                int kb   = ks * 32 + (lane >> 4) * 16;
#pragma unroll
                for (int mt = 0; mt < 4; ++mt)
                    ldm4(afr[mt],
                         bufA + SWZ((uint32_t)((arow + mt * 16) * 128 + kb)));
            }
            uint32_t bfr[4][2];
            {
                int j    = lane >> 3;
                int brow = (j >> 1) * 8 + (lane & 7);
                int kb   = ks * 32 + (j & 1) * 16;
#pragma unroll
                for (int p = 0; p < 2; ++p) {
                    uint32_t r[4];
                    ldm4(r, bufB +
                            SWZ((uint32_t)((wn * 32 + p * 16 + brow) * 128 + kb)));
                    bfr[p * 2][0]     = r[0];
                    bfr[p * 2][1]     = r[1];
                    bfr[p * 2 + 1][0] = r[2];
                    bfr[p * 2 + 1][1] = r[3];
                }
            }
#pragma unroll
            for (int mt = 0; mt < 4; ++mt)
#pragma unroll
                for (int nt = 0; nt < 4; ++nt)
                    mma_bf16(acc[mt][nt], afr[mt], bfr[nt]);
        }
        __syncthreads();
    }

#pragma unroll
    for (int nt = 0; nt < 4; ++nt) {
        int n0 = col0 + wn * 32 + nt * 8 + (lane & 3) * 2;
        float b0 = bih[n0] + bhh[n0];
        float b1 = bih[n0 + 1] + bhh[n0 + 1];
        size_t plane = (size_t)(n0 >> 4) * RTOT;
        int cc = n0 & 15;
#pragma unroll
        for (int mt = 0; mt < 4; ++mt) {
            int r0 = row0 + wm * 64 + mt * 16 + (lane >> 2);
            float2 v0 = make_float2(acc[mt][nt][0] + b0, acc[mt][nt][1] + b1);
            float2 v1 = make_float2(acc[mt][nt][2] + b0, acc[mt][nt][3] + b1);
            *(float2*)&g_xg[(plane + r0) * 16 + cc]     = v0;
            *(float2*)&g_xg[(plane + r0 + 8) * 16 + cc] = v1;
        }
    }
}

// ---------------------------------------------------------------------------
// Persistent recurrent scan with PER-ROW-GROUP barriers and seed prefetch.
// Block (cg, rg): cg = bid % NCG owns CW h-columns, rg = bid / NCG owns RW
// contiguous rows. Only the NCG blocks sharing rg must synchronize per step
// (consumers read h rows of their own rg only).
// Per step: poll rg-gen -> stage h slab -> gates from SMEM (f32x2) -> cell
// -> h via Ssm coalesced STG -> sync -> release-arrive -> prefetch next
// step's xg seeds into the alternate Xsm buffer (hidden in barrier shadow).
// ---------------------------------------------------------------------------
template <int MB, int CW, int RPT>
__global__ void __launch_bounds__(256, 1) scan_kernel(
    const float* __restrict__ Whh,   // [1024, 256] row-major
    float* __restrict__ out,         // [nsteps*MB, 256]
    int nsteps)
{
    constexpr int RPW = 256 / CW;        // row slots per column
    constexpr int RW  = RPW * RPT;       // rows per block
    constexpr int NCG = 256 / CW;        // column groups = barrier group size
    constexpr int CWP = (CW == 16) ? 18 : 36;  // conflict-free padded stride
    constexpr int NSL = CW / 16;         // 16-col planes per block

    extern __shared__ float smemf[];
    float* Wsm = smemf;                          // [4*CW][SPAD]
    float* Hsm = Wsm + 4 * CW * SPAD;            // [RW][SPAD]
    float* Xsm = Hsm + RW * SPAD;                // [2][4*RW][CWP]
    float* Ssm = Xsm + 2 * 4 * RW * CWP;         // [RW][CWP]

    const int tid     = threadIdx.x;
    const int cg      = blockIdx.x % NCG;
    const int rg      = blockIdx.x / NCG;
    const int gc0     = cg * CW;
    const int rowbase = rg * RW;
    const int c       = tid / RPW;       // owned column (0..CW-1)
    const int q       = tid % RPW;       // row slot

    unsigned* bcnt = &g_rgbar[rg * 64];
    unsigned* bgen = &g_rgbar[rg * 64 + 32];
    // Safe: this rg's gen cannot advance until THIS block arrives.
    const unsigned gbase = ld_acq(bgen);

    for (int idx = tid; idx < 4 * CW * 64; idx += 256) {
        int k4 = idx % 64;
        int cc = (idx / 64) % CW;
        int g  = idx / (64 * CW);
        float4 v = *(const float4*)&Whh[(size_t)(g * 256 + gc0 + cc) * HH + k4 * 4];
        *(float4*)&Wsm[(g * CW + cc) * SPAD + k4 * 4] = v;
    }

    // Pre-stage step-0 seeds into Xsm[0]
    {
        for (int idx = tid; idx < 4 * NSL * RW * 4; idx += 256) {
            int c4   = idx & 3;
            int r    = (idx >> 2) % RW;
            int rest = idx / (4 * RW);
            int cgi  = rest % NSL;
            int g    = rest / NSL;
            const float* src =
                &g_xg[((size_t)(g * 16 + cg * NSL + cgi) * RTOT + rowbase + r) * 16
                      + c4 * 4];
            float4 v = *(const float4*)src;
            float* dst = &Xsm[(g * RW + r) * CWP + cgi * 16 + c4 * 4];
            dst[0] = v.x; dst[1] = v.y; dst[2] = v.z; dst[3] = v.w;
        }
    }

    float c_st[RPT];
#pragma unroll
    for (int j = 0; j < RPT; ++j) c_st[j] = 0.f;

    for (int step = 0; step < nsteps; ++step) {
        const int buf = step & 1;

        if (step > 0) {
            // All threads poll the row-group generation (broadcast load).
            const unsigned target = gbase + (unsigned)step;
            while ((int)(ld_acq(bgen) - target) < 0) { }
            // Stage h_prev slab (coalesced float4)
            const float* hp = out + ((size_t)(step - 1) * MB + rowbase) * HH;
            for (int idx = tid; idx < RW * 64; idx += 256) {
                int r  = idx / 64;
                int k4 = idx % 64;
                float4 v = *(const float4*)&hp[r * HH + k4 * 4];
                *(float4*)&Hsm[r * SPAD + k4 * 4] = v;
            }
        }
        __syncthreads();   // Hsm + Xsm[buf] ready

        const float* Xb = Xsm + buf * 4 * RW * CWP;
        ull acc[RPT][4];
#pragma unroll
        for (int j = 0; j < RPT; ++j)
#pragma unroll
            for (int g = 0; g < 4; ++g)
                acc[j][g] =
                    (ull)__float_as_uint(Xb[(g * RW + q + j * RPW) * CWP + c]);

        if (step > 0) {
#pragma unroll 2
            for (int k4 = 0; k4 < 64; ++k4) {
                ulonglong2 w[4];
#pragma unroll
                for (int g = 0; g < 4; ++g)
                    w[g] = *(const ulonglong2*)&Wsm[(g * CW + c) * SPAD + k4 * 4];
#pragma unroll
                for (int j = 0; j < RPT; ++j) {
                    ulonglong2 h2 =
                        *(const ulonglong2*)&Hsm[(q + j * RPW) * SPAD + k4 * 4];
#pragma unroll
                    for (int g = 0; g < 4; ++g) {
                        fma2(acc[j][g], h2.x, w[g].x);
                        fma2(acc[j][g], h2.y, w[g].y);
                    }
                }
            }
        }

        // LSTM cell -> stage h into Ssm
#pragma unroll
        for (int j = 0; j < RPT; ++j) {
            float2 pi = unpack2(acc[j][0]);
            float2 pf = unpack2(acc[j][1]);
            float2 pg = unpack2(acc[j][2]);
            float2 po = unpack2(acc[j][3]);
            float vi = pi.x + pi.y;
            float vf = pf.x + pf.y;
            float vg = pg.x + pg.y;
            float vo = po.x + po.y;
            float ig = sigf(vi);
            float fg = sigf(vf);
            float gt = tanh_fast(vg);
            float og = sigf(vo);
            float cc2 = fg * c_st[j] + ig * gt;
            c_st[j] = cc2;
            Ssm[(q + j * RPW) * CWP + c] = og * tanh_fast(cc2);
        }
        __syncthreads();   // Ssm ready; also: everyone done with Hsm/Xsm[buf]

        // Coalesced h store
        {
            float* orow = out + ((size_t)step * MB + rowbase) * HH + gc0;
            for (int idx = tid; idx < RW * (CW / 4); idx += 256) {
                int c4 = idx % (CW / 4);
                int r  = idx / (CW / 4);
                const float* s = &Ssm[r * CWP + c4 * 4];
                float4 v = make_float4(s[0], s[1], s[2], s[3]);
                *(float4*)&orow[(size_t)r * HH + c4 * 4] = v;
            }
        }
        __syncthreads();   // all h stores issued, block-visible

        if (step + 1 < nsteps) {
            // Release-arrive on the row-group barrier (thread 0)
            if (tid == 0) {
                __threadfence();
                if (atomicAdd(bcnt, 1u) == (unsigned)(NCG - 1)) {
                    atomicExch(bcnt, 0u);
                    __threadfence();
                    atomicAdd(bgen, 1u);
                }
            }
            // Prefetch next step's seeds into the alternate buffer while the
            // row-group barrier drains (fully hidden off the critical path).
            const size_t srow0 = (size_t)(step + 1) * MB + rowbase;
            float* Xn = Xsm + (1 - buf) * 4 * RW * CWP;
            for (int idx = tid; idx < 4 * NSL * RW * 4; idx += 256) {
                int c4   = idx & 3;
                int r    = (idx >> 2) % RW;
                int rest = idx / (4 * RW);
                int cgi  = rest % NSL;
                int g    = rest / NSL;
                const float* src =
                    &g_xg[((size_t)(g * 16 + cg * NSL + cgi) * RTOT + srow0 + r) * 16
                          + c4 * 4];
                float4 v = *(const float4*)src;
                float* dst = &Xn[(g * RW + r) * CWP + cgi * 16 + c4 * 4];
                dst[0] = v.x; dst[1] = v.y; dst[2] = v.z; dst[3] = v.w;
            }
        }
    }
}

// ---------------------------------------------------------------------------
// kernel_launch: per layer: split-convert A & W -> HMMA GEMM -> scan.
// Graph-capturable, allocation-free, deterministic.
// ---------------------------------------------------------------------------
extern "C" void kernel_launch(void* const* d_in, const int* in_sizes, int n_in,
                              void* d_out, int out_size)
{
    (void)in_sizes; (void)n_in; (void)out_size;
    const float* x    = (const float*)d_in[0];
    const float* Wih0 = (const float*)d_in[1];
    const float* Whh0 = (const float*)d_in[2];
    const float* bih0 = (const float*)d_in[3];
    const float* bhh0 = (const float*)d_in[4];
    const float* Wih1 = (const float*)d_in[5];
    const float* Whh1 = (const float*)d_in[6];
    const float* bih1 = (const float*)d_in[7];
    const float* bhh1 = (const float*)d_in[8];
    const float* Wih2 = (const float*)d_in[9];
    const float* Whh2 = (const float*)d_in[10];
    const float* bih2 = (const float*)d_in[11];
    const float* bhh2 = (const float*)d_in[12];
    float* out = (float*)d_out;

    float* tmp = nullptr;
    cudaGetSymbolAddress((void**)&tmp, g_tmp);
    __nv_bfloat16 *Ah = nullptr, *Al = nullptr, *Wh = nullptr, *Wl = nullptr;
    cudaGetSymbolAddress((void**)&Ah, g_Ah);
    cudaGetSymbolAddress((void**)&Al, g_Al);
    cudaGetSymbolAddress((void**)&Wh, g_Wh);
    cudaGetSymbolAddress((void**)&Wl, g_Wl);

    // Scan SMEM: (4*CW + RW)*SPAD + (2*4+1)*RW*CWP floats
    const int smem0 = ((4 * 16 + 16) * SPAD + 9 * 16 * 18) * 4;   //  93952 B
    const int smem1 = ((4 * 32 + 16) * SPAD + 9 * 16 * 36) * 4;   // 170496 B
    const int smem2 = ((4 * 32 + 32) * SPAD + 9 * 32 * 36) * 4;   // 207872 B
    cudaFuncSetAttribute((const void*)scan_kernel<128, 16, 1>,
                         cudaFuncAttributeMaxDynamicSharedMemorySize, smem0);
    cudaFuncSetAttribute((const void*)scan_kernel<256, 32, 2>,
                         cudaFuncAttributeMaxDynamicSharedMemorySize, smem1);
    cudaFuncSetAttribute((const void*)scan_kernel<512, 32, 4>,
                         cudaFuncAttributeMaxDynamicSharedMemorySize, smem2);

    const int gsm = 1024 + 2 * 32768;
    cudaFuncSetAttribute((const void*)gemm_hmma_kernel<128>,
                         cudaFuncAttributeMaxDynamicSharedMemorySize, gsm);
    cudaFuncSetAttribute((const void*)gemm_hmma_kernel<256>,
                         cudaFuncAttributeMaxDynamicSharedMemorySize, gsm);

    dim3 ggrid(8, 1024);   // 128-col x 128-row tiles over [131072 x 1024]

    // ---- Layer 0: K=128, MB=128, 1024 steps
    {
        int n4a = RTOT * 128 / 4;
        convert_split_kernel<<<(n4a + 255) / 256, 256>>>(x, Ah, Al, n4a);
        int n4w = 1024 * 128 / 4;
        convert_split_kernel<<<(n4w + 255) / 256, 256>>>(Wih0, Wh, Wl, n4w);
        gemm_hmma_kernel<128><<<ggrid, 256, gsm>>>(bih0, bhh0);
        scan_kernel<128, 16, 1><<<128, 256, smem0>>>(Whh0, tmp, 1024);
    }
    // ---- Layer 1: K=256, MB=256, 512 steps
    {
        int n4a = RTOT * 256 / 4;
        convert_split_kernel<<<(n4a + 255) / 256, 256>>>(tmp, Ah, Al, n4a);
        int n4w = 1024 * 256 / 4;
        convert_split_kernel<<<(n4w + 255) / 256, 256>>>(Wih1, Wh, Wl, n4w);
        gemm_hmma_kernel<256><<<ggrid, 256, gsm>>>(bih1, bhh1);
        scan_kernel<256, 32, 2><<<128, 256, smem1>>>(Whh1, tmp, 512);
    }
    // ---- Layer 2: K=256, MB=512, 256 steps (writes final output)
    {
        int n4a = RTOT * 256 / 4;
        convert_split_kernel<<<(n4a + 255) / 256, 256>>>(tmp, Ah, Al, n4a);
        int n4w = 1024 * 256 / 4;
        convert_split_kernel<<<(n4w + 255) / 256, 256>>>(Wih2, Wh, Wl, n4w);
        gemm_hmma_kernel<256><<<ggrid, 256, gsm>>>(bih2, bhh2);
        scan_kernel<512, 32, 4><<<128, 256, smem2>>>(Whh2, out, 256);
    }
}